// round 14
// baseline (speedup 1.0000x reference)
#include <cuda_runtime.h>
#include <cuda_fp16.h>
#include <math.h>
#include <stdint.h>

#define NPTS 4096
#define DS 48
#define DA 16
#define DF 64
#define TB 128
#define NTILE (NPTS / TB)      /* 32 */
#define NB1 2048               /* coarse bins over [0,16] */
#define SC1 128.0f             /* NB1/16 */
#define NBF 8192               /* fine bins in refine pass */

// ---------------- device scratch ----------------
__device__ __half g_hA[(size_t)NPTS * DF];
__device__ __half g_hB[(size_t)NPTS * DF];
__device__ float  g_x2[NPTS];
__device__ float  g_y2[NPTS];
__device__ float  g_hcoarse[2 * NB1];
__device__ float  g_hfine[2 * NBF];
__device__ double g_below[2];
__device__ double g_scal[8];   // 0 Wsum,1 EWsum,2/3 lo/width ae,4/5 lo/width ee,6 g1,7 g2
__device__ float  g_Sae[NPTS];
__device__ float  g_Saa[NPTS];

// ---------------- mma / ldmatrix helpers (fp16 in, fp32 accum) ----------------
#define MMA_AB(d, A, b0, b1)                                                \
    asm volatile(                                                           \
        "mma.sync.aligned.m16n8k16.row.col.f32.f16.f16.f32 "                \
        "{%0,%1,%2,%3}, {%4,%5,%6,%7}, {%8,%9}, {%0,%1,%2,%3};"             \
        : "+f"((d)[0]), "+f"((d)[1]), "+f"((d)[2]), "+f"((d)[3])            \
        : "r"((A)[0]), "r"((A)[1]), "r"((A)[2]), "r"((A)[3]), "r"(b0), "r"(b1))

__device__ __forceinline__ void ldsm4(uint32_t a, uint32_t d[4]) {
    asm volatile("ldmatrix.sync.aligned.m8n8.x4.shared.b16 {%0,%1,%2,%3}, [%4];"
                 : "=r"(d[0]), "=r"(d[1]), "=r"(d[2]), "=r"(d[3]) : "r"(a));
}

#define SWO(r, kc) ((uint32_t)(r) * 128u + (((uint32_t)(kc)) ^ (((uint32_t)(r) & 7u) << 4)))
#define TILE_BYTES 16384

// ---------------- staging: global (row-major 128B rows) -> swizzled smem tile ----------------
__device__ __forceinline__ void stage_one(char* dst, const __half* src,
                                          int row0, int rstride, int tid, int nrows) {
    const uint4* p = (const uint4*)src;
    for (int idx = tid; idx < nrows * 8; idx += 256) {
        int r = idx >> 3, c = idx & 7;
        uint32_t off = (uint32_t)r * 128u + (((uint32_t)c * 16u) ^ (((uint32_t)r & 7u) << 4));
        *(uint4*)(dst + off) = p[(size_t)(row0 + r * rstride) * 8 + c];
    }
}

// ---------------- mainloop: single-product fp16 mma ----------------
template <int MF>
__device__ __forceinline__ void mma_loop(uint32_t sA, uint32_t sB,
                                         int tid, float acc[4][4][4]) {
    const int lane = tid & 31, warp = tid >> 5;
    const int wr = warp >> 2, wc = warp & 3;

    #pragma unroll
    for (int mf = 0; mf < MF; mf++)
        #pragma unroll
        for (int nf = 0; nf < 4; nf++)
            #pragma unroll
            for (int u = 0; u < 4; u++) acc[mf][nf][u] = 0.f;

    const int aRow = lane & 15;
    const int aKc  = (lane >> 4) << 4;
    const int bRow = ((lane & 16) >> 1) + (lane & 7);
    const int bKc  = (lane & 8) ? 16 : 0;

    #pragma unroll
    for (int ks = 0; ks < 4; ks++) {
        const int kc0 = ks * 32;
        uint32_t BH[2][4];
        #pragma unroll
        for (int p = 0; p < 2; p++) {
            uint32_t off = SWO(wc * 32 + p * 16 + bRow, kc0 + bKc);
            ldsm4(sB + off, BH[p]);
        }
        #pragma unroll
        for (int mf = 0; mf < MF; mf++) {
            uint32_t off = SWO(wr * (MF * 16) + mf * 16 + aRow, kc0 + aKc);
            uint32_t AH[4];
            ldsm4(sA + off, AH);
            #pragma unroll
            for (int p = 0; p < 2; p++) {
                MMA_AB(acc[mf][2 * p],     AH, BH[p][0], BH[p][1]);
                MMA_AB(acc[mf][2 * p + 1], AH, BH[p][2], BH[p][3]);
            }
        }
    }
}

// ---------------- convert inputs to fp16 + row norms + zero accumulators ----------------
__global__ void k_cvt(const float* __restrict__ ss, const float* __restrict__ aa_,
                      const float* __restrict__ es, const float* __restrict__ ea) {
    __shared__ float cvt_part[8];
    int tid = threadIdx.x;
    int gid = blockIdx.x * 256 + tid;
    if (gid < 2 * NB1) g_hcoarse[gid] = 0.f;
    if (gid < 2 * NBF) g_hfine[gid]   = 0.f;
    if (gid < NPTS)  { g_Saa[gid] = 0.f; g_Sae[gid] = 0.f; }
    if (gid < 2)       g_below[gid]   = 0.0;

    int gr = blockIdx.x * 4 + (tid >> 6);
    int k  = tid & 63;
    bool isA = (gr < NPTS);
    int r = isA ? gr : gr - NPTS;
    const float* sp = isA ? ss : es;
    const float* ap = isA ? aa_ : ea;
    __half* hp = isA ? g_hA : g_hB;

    float v = (k < DS) ? sp[(size_t)r * DS + k] : ap[(size_t)r * DA + (k - DS)];
    hp[(size_t)r * DF + k] = __float2half(v);

    float sq = v * v;
    #pragma unroll
    for (int off = 16; off; off >>= 1) sq += __shfl_xor_sync(0xFFFFFFFF, sq, off);
    if ((tid & 31) == 0) cvt_part[tid >> 5] = sq;
    __syncthreads();
    if ((tid & 63) == 0) {
        float s = cvt_part[(tid >> 5)] + cvt_part[(tid >> 5) + 1];
        if (isA) g_x2[r] = s; else g_y2[r] = s;
    }
}

// ---------------- sampled coarse hist via fp16 MMA, M=64 tiles ----------------
#define HOF_X2    0
#define HOF_WX    256
#define HOF_Y2    512
#define HOF_WY    1024
#define HOF_HIST  1536
#define HOF_TILES 17920
#define SMEM_HS   (HOF_TILES + 8192 + 16384)   /* 42496 */

__global__ void __launch_bounds__(256) k_hist_sampled(
    const float* __restrict__ w, const float* __restrict__ ew)
{
    extern __shared__ __align__(128) char smem[];
    int tid = threadIdx.x;
    bool ae = (blockIdx.z == 0);
    int col0 = blockIdx.x * TB;
    int sbase = blockIdx.y * 64;

    const __half* Ah = ae ? g_hA : g_hB;
    const float* x2p = ae ? g_x2 : g_y2;
    const float* wxp = ae ? w : ew;

    float* shh = (float*)(smem + HOF_HIST);
    for (int i = tid; i < 2 * NB1; i += 256) shh[i] = 0.f;

    stage_one(smem + HOF_TILES,        Ah,   sbase * 16, 16, tid, 64);
    stage_one(smem + HOF_TILES + 8192, g_hB, col0,       1,  tid, 128);
    if (tid < 64) {
        ((float*)(smem + HOF_X2))[tid] = x2p[(sbase + tid) * 16];
        ((float*)(smem + HOF_WX))[tid] = wxp[(sbase + tid) * 16];
    }
    if (tid < TB) {
        ((float*)(smem + HOF_Y2))[tid] = g_y2[col0 + tid];
        ((float*)(smem + HOF_WY))[tid] = ew[col0 + tid];
    }
    __syncthreads();

    uint32_t sT = (uint32_t)__cvta_generic_to_shared(smem) + HOF_TILES;
    float acc[4][4][4];
    mma_loop<2>(sT, sT + 8192, tid, acc);

    const int lane = tid & 31, warp = tid >> 5;
    const int wr = warp >> 2, wc = warp & 3;
    const int g = lane >> 2, t = lane & 3;
    const float* x2s = (const float*)(smem + HOF_X2);
    const float* wxs = (const float*)(smem + HOF_WX);
    const float* y2s = (const float*)(smem + HOF_Y2);
    const float* wys = (const float*)(smem + HOF_WY);
    float* myh = shh + (warp & 1) * NB1;

    #pragma unroll
    for (int mf = 0; mf < 2; mf++) {
        int r0 = wr * 32 + mf * 16 + g;
        float x0 = x2s[r0], x1 = x2s[r0 + 8];
        float wx0 = wxs[r0], wx1 = wxs[r0 + 8];
        #pragma unroll
        for (int nf = 0; nf < 4; nf++) {
            int c0 = wc * 32 + nf * 8 + 2 * t;
            float y0 = y2s[c0], y1 = y2s[c0 + 1];
            float wy0 = wys[c0], wy1 = wys[c0 + 1];
            float d00 = fmaxf(x0 + y0 - 2.f * acc[mf][nf][0], 0.f) * (1.f / DF);
            float d01 = fmaxf(x0 + y1 - 2.f * acc[mf][nf][1], 0.f) * (1.f / DF);
            float d10 = fmaxf(x1 + y0 - 2.f * acc[mf][nf][2], 0.f) * (1.f / DF);
            float d11 = fmaxf(x1 + y1 - 2.f * acc[mf][nf][3], 0.f) * (1.f / DF);
            atomicAdd(&myh[min((int)(d00 * SC1), NB1 - 1)], wx0 * wy0);
            atomicAdd(&myh[min((int)(d01 * SC1), NB1 - 1)], wx0 * wy1);
            atomicAdd(&myh[min((int)(d10 * SC1), NB1 - 1)], wx1 * wy0);
            atomicAdd(&myh[min((int)(d11 * SC1), NB1 - 1)], wx1 * wy1);
        }
    }
    __syncthreads();
    float* hist = g_hcoarse + (ae ? 0 : NB1);
    for (int i = tid; i < NB1; i += 256) {
        float v = shh[i] + shh[i + NB1];
        if (v != 0.f) atomicAdd(&hist[i], v);
    }
}

// ---------------- scan coarse hist -> window (±16 bins); also weight sums ----------------
__global__ void k_scan0(const float* __restrict__ w, const float* __restrict__ ew) {
    int which = blockIdx.x;
    int tid = threadIdx.x;
    __shared__ double part[256];

    // fold weight sum (block 0: w, block 1: ew)
    {
        const float* src = which ? ew : w;
        double s = 0.0;
        for (int i = tid; i < NPTS; i += 256) s += src[i];
        part[tid] = s; __syncthreads();
        for (int off = 128; off; off >>= 1) {
            if (tid < off) part[tid] += part[tid + off];
            __syncthreads();
        }
        if (tid == 0) g_scal[which] = part[0];
        __syncthreads();
    }

    const float* h = g_hcoarse + which * NB1;
    double loc[8], s = 0.0;
    #pragma unroll
    for (int i = 0; i < 8; i++) { loc[i] = h[tid * 8 + i]; s += loc[i]; }
    part[tid] = s; __syncthreads();
    for (int off = 1; off < 256; off <<= 1) {
        double v = (tid >= off) ? part[tid - off] : 0.0;
        __syncthreads();
        part[tid] += v;
        __syncthreads();
    }
    double T = 0.5 * part[255];
    double c = tid ? part[tid - 1] : 0.0;
    int b = -1;
    #pragma unroll
    for (int i = 0; i < 8; i++) {
        double nc = c + loc[i];
        if (b < 0 && c < T && nc >= T) b = tid * 8 + i;
        c = nc;
    }
    if (b >= 0) {
        int blo = b > 16 ? b - 16 : 0;
        int bhi = b + 17 > NB1 ? NB1 : b + 17;
        g_scal[2 + 2 * which] = blo * (16.0 / NB1);
        g_scal[3 + 2 * which] = (bhi - blo) * (16.0 / NB1);
    }
}

// ---------------- fused refine: shared B col tile, phases ae (A=hA) / ee (A=hB) ------------
#define ROF_X2AE  0
#define ROF_X2EE  512
#define ROF_Y2    1024
#define ROF_WXAE  1536
#define ROF_WXEE  2048
#define ROF_WY    2560
#define ROF_HIST  3072                       /* NBF*4 = 32768 */
#define ROF_TILES 35840
#define SMEM_RF   (ROF_TILES + 3 * TILE_BYTES)   /* 84992 */

__global__ void __launch_bounds__(256) k_refine_fused(
    const float* __restrict__ w, const float* __restrict__ ew)
{
    extern __shared__ __align__(128) char smem[];
    __shared__ float red[256];
    int tid = threadIdx.x;
    int row0 = blockIdx.y * TB, col0 = blockIdx.x * TB;

    float* shh = (float*)(smem + ROF_HIST);
    for (int i = tid; i < NBF; i += 256) shh[i] = 0.f;

    stage_one(smem + ROF_TILES,                  g_hA, row0, 1, tid, 128);  // A_ae
    stage_one(smem + ROF_TILES + TILE_BYTES,     g_hB, row0, 1, tid, 128);  // A_ee
    stage_one(smem + ROF_TILES + 2 * TILE_BYTES, g_hB, col0, 1, tid, 128);  // B (shared)
    if (tid < TB) {
        ((float*)(smem + ROF_X2AE))[tid] = g_x2[row0 + tid];
        ((float*)(smem + ROF_X2EE))[tid] = g_y2[row0 + tid];
        ((float*)(smem + ROF_Y2))[tid]   = g_y2[col0 + tid];
        ((float*)(smem + ROF_WXAE))[tid] = w[row0 + tid];
        ((float*)(smem + ROF_WXEE))[tid] = ew[row0 + tid];
        ((float*)(smem + ROF_WY))[tid]   = ew[col0 + tid];
    }
    __syncthreads();

    uint32_t sT = (uint32_t)__cvta_generic_to_shared(smem) + ROF_TILES;
    const int lane = tid & 31, warp = tid >> 5;
    const int wr = warp >> 2, wc = warp & 3;
    const int g = lane >> 2, t = lane & 3;
    const float* y2s = (const float*)(smem + ROF_Y2);
    const float* wys = (const float*)(smem + ROF_WY);

    #pragma unroll
    for (int phase = 0; phase < 2; phase++) {
        int which = phase;     // 0 ae, 1 ee
        const float* x2s = (const float*)(smem + (phase ? ROF_X2EE : ROF_X2AE));
        const float* wxs = (const float*)(smem + (phase ? ROF_WXEE : ROF_WXAE));
        float lo    = (float)g_scal[2 + 2 * which];
        float scale = (float)((double)NBF / g_scal[3 + 2 * which]);

        float acc[4][4][4];
        mma_loop<4>(sT + phase * TILE_BYTES, sT + 2 * TILE_BYTES, tid, acc);

        float bacc = 0.f;
        #pragma unroll
        for (int mf = 0; mf < 4; mf++) {
            int r0 = wr * 64 + mf * 16 + g;
            float x0 = x2s[r0], x1 = x2s[r0 + 8];
            float wx0 = wxs[r0], wx1 = wxs[r0 + 8];
            #pragma unroll
            for (int nf = 0; nf < 4; nf++) {
                int c0 = wc * 32 + nf * 8 + 2 * t;
                float y0 = y2s[c0], y1 = y2s[c0 + 1];
                float wy0 = wys[c0], wy1 = wys[c0 + 1];
                float dd[4], wt[4];
                dd[0] = fmaxf(x0 + y0 - 2.f * acc[mf][nf][0], 0.f) * (1.f / DF); wt[0] = wx0 * wy0;
                dd[1] = fmaxf(x0 + y1 - 2.f * acc[mf][nf][1], 0.f) * (1.f / DF); wt[1] = wx0 * wy1;
                dd[2] = fmaxf(x1 + y0 - 2.f * acc[mf][nf][2], 0.f) * (1.f / DF); wt[2] = wx1 * wy0;
                dd[3] = fmaxf(x1 + y1 - 2.f * acc[mf][nf][3], 0.f) * (1.f / DF); wt[3] = wx1 * wy1;
                #pragma unroll
                for (int u = 0; u < 4; u++) {
                    if (dd[u] < lo) bacc += wt[u];
                    else {
                        int b = (int)((dd[u] - lo) * scale);
                        if (b < NBF) atomicAdd(&shh[b], wt[u]);
                    }
                }
            }
        }
        red[tid] = bacc; __syncthreads();
        for (int off = 128; off; off >>= 1) {
            if (tid < off) red[tid] += red[tid + off];
            __syncthreads();
        }
        if (tid == 0) atomicAdd(&g_below[which], (double)red[0]);
        float* hist = g_hfine + which * NBF;
        for (int i = tid; i < NBF; i += 256) {
            float v = shh[i];
            if (v != 0.f) atomicAdd(&hist[i], v);
            if (phase == 0) shh[i] = 0.f;     // re-zero for phase 1
        }
        __syncthreads();
    }
}

// ---------------- scan fine hist -> g ----------------
__global__ void k_scanF() {
    int which = blockIdx.x;
    const float* h = g_hfine + which * NBF;
    __shared__ double part[1024];
    int tid = threadIdx.x;
    double loc[8], s = 0.0;
    #pragma unroll
    for (int i = 0; i < 8; i++) { loc[i] = h[tid * 8 + i]; s += loc[i]; }
    part[tid] = s; __syncthreads();
    for (int off = 1; off < 1024; off <<= 1) {
        double v = (tid >= off) ? part[tid - off] : 0.0;
        __syncthreads();
        part[tid] += v;
        __syncthreads();
    }
    double Wtot = (which == 0) ? g_scal[0] * g_scal[1] : g_scal[1] * g_scal[1];
    double T = 0.5 * Wtot - g_below[which];
    double lo = g_scal[2 + 2 * which], wdt = g_scal[3 + 2 * which];
    double c = tid ? part[tid - 1] : 0.0;
    int b = -1;
    #pragma unroll
    for (int i = 0; i < 8; i++) {
        double nc = c + loc[i];
        if (b < 0 && c < T && nc >= T) b = tid * 8 + i;
        c = nc;
    }
    if (tid == 0 && T <= 0.0) b = 0;
    if (tid == 1023 && T > 0.0 && part[1023] < T && b < 0) b = NBF - 1;
    if (b >= 0) {
        double tt = lo + (b + 0.5) * (wdt / NBF);
        g_scal[6 + which] = 1.0 / (tt + 1e-8);
    }
}

// ---------------- fused final: shared A row tile, phases ae (B=hB) / aa (B=hA) ------------
#define FOF_X2    0
#define FOF_Y2AE  512
#define FOF_Y2AA  1024
#define FOF_WAE   1536
#define FOF_WAA   2048
#define FOF_RS    2560
#define FOF_TILES 3072
#define SMEM_FIN  (FOF_TILES + 3 * TILE_BYTES)   /* 52224 */

__global__ void __launch_bounds__(256) k_final_fused(
    const float* __restrict__ w, const float* __restrict__ ew)
{
    extern __shared__ __align__(128) char smem[];
    int tid = threadIdx.x;
    int row0 = blockIdx.y * TB, col0 = blockIdx.x * TB;

    stage_one(smem + FOF_TILES,                  g_hA, row0, 1, tid, 128);  // A (shared)
    stage_one(smem + FOF_TILES + TILE_BYTES,     g_hB, col0, 1, tid, 128);  // B_ae
    stage_one(smem + FOF_TILES + 2 * TILE_BYTES, g_hA, col0, 1, tid, 128);  // B_aa
    if (tid < TB) {
        ((float*)(smem + FOF_X2))[tid]   = g_x2[row0 + tid];
        ((float*)(smem + FOF_Y2AE))[tid] = g_y2[col0 + tid];
        ((float*)(smem + FOF_Y2AA))[tid] = g_x2[col0 + tid];
        ((float*)(smem + FOF_WAE))[tid]  = ew[col0 + tid];
        ((float*)(smem + FOF_WAA))[tid]  = w[col0 + tid];
        ((float*)(smem + FOF_RS))[tid]   = 0.f;
    }
    __syncthreads();

    uint32_t sT = (uint32_t)__cvta_generic_to_shared(smem) + FOF_TILES;
    const int lane = tid & 31, warp = tid >> 5;
    const int wr = warp >> 2, wc = warp & 3;
    const int g = lane >> 2, t = lane & 3;
    const float* x2s = (const float*)(smem + FOF_X2);
    float* rowsum = (float*)(smem + FOF_RS);

    float G1 = (float)g_scal[6], G2 = (float)g_scal[7];

    #pragma unroll
    for (int phase = 0; phase < 2; phase++) {
        const float* y2s = (const float*)(smem + (phase ? FOF_Y2AA : FOF_Y2AE));
        const float* ws  = (const float*)(smem + (phase ? FOF_WAA : FOF_WAE));

        float acc[4][4][4];
        mma_loop<4>(sT, sT + (1 + phase) * TILE_BYTES, tid, acc);

        #pragma unroll
        for (int mf = 0; mf < 4; mf++) {
            int r0 = wr * 64 + mf * 16 + g;
            float x0 = x2s[r0], x1 = x2s[r0 + 8];
            float p0 = 0.f, p1 = 0.f;
            #pragma unroll
            for (int nf = 0; nf < 4; nf++) {
                int c0 = wc * 32 + nf * 8 + 2 * t;
                float y0 = y2s[c0], y1 = y2s[c0 + 1];
                float w0 = ws[c0],  w1 = ws[c0 + 1];
                float d00 = fmaxf(x0 + y0 - 2.f * acc[mf][nf][0], 0.f) * (1.f / DF);
                float d01 = fmaxf(x0 + y1 - 2.f * acc[mf][nf][1], 0.f) * (1.f / DF);
                float d10 = fmaxf(x1 + y0 - 2.f * acc[mf][nf][2], 0.f) * (1.f / DF);
                float d11 = fmaxf(x1 + y1 - 2.f * acc[mf][nf][3], 0.f) * (1.f / DF);
                p0 += (__expf(-G1 * d00) + __expf(-G2 * d00)) * w0
                    + (__expf(-G1 * d01) + __expf(-G2 * d01)) * w1;
                p1 += (__expf(-G1 * d10) + __expf(-G2 * d10)) * w0
                    + (__expf(-G1 * d11) + __expf(-G2 * d11)) * w1;
            }
            atomicAdd(&rowsum[r0], p0);
            atomicAdd(&rowsum[r0 + 8], p1);
        }
        __syncthreads();
        if (tid < TB) {
            float* Sout = phase ? g_Saa : g_Sae;
            atomicAdd(&Sout[row0 + tid], rowsum[tid]);
            rowsum[tid] = 0.f;     // re-zero for phase 1
        }
        __syncthreads();
    }
}

// ---------------- final combine ----------------
__global__ void k_combine(const float* __restrict__ w, float* __restrict__ out) {
    int i = blockIdx.x * blockDim.x + threadIdx.x;
    if (i < NPTS) {
        float Ws  = (float)g_scal[0];
        float EWs = (float)g_scal[1];
        out[i] = (w[i] / Ws) * (g_Sae[i] / EWs - g_Saa[i] / Ws);
    }
}

// ---------------- host launcher ----------------
extern "C" void kernel_launch(void* const* d_in, const int* in_sizes, int n_in,
                              void* d_out, int out_size)
{
    const float* state   = (const float*)d_in[0];
    const float* action  = (const float*)d_in[1];
    const float* estate  = (const float*)d_in[2];
    const float* eaction = (const float*)d_in[3];
    const float* w       = (const float*)d_in[4];
    const float* ew      = (const float*)d_in[5];
    float* out = (float*)d_out;

    cudaFuncSetAttribute(k_hist_sampled, cudaFuncAttributeMaxDynamicSharedMemorySize, SMEM_HS);
    cudaFuncSetAttribute(k_refine_fused, cudaFuncAttributeMaxDynamicSharedMemorySize, SMEM_RF);
    cudaFuncSetAttribute(k_final_fused,  cudaFuncAttributeMaxDynamicSharedMemorySize, SMEM_FIN);

    dim3 ghs(NTILE, 4, 2);
    dim3 gtile(NTILE, NTILE);

    k_cvt<<<2048, 256>>>(state, action, estate, eaction);
    k_hist_sampled<<<ghs, 256, SMEM_HS>>>(w, ew);
    k_scan0<<<2, 256>>>(w, ew);
    k_refine_fused<<<gtile, 256, SMEM_RF>>>(w, ew);
    k_scanF<<<2, 1024>>>();
    k_final_fused<<<gtile, 256, SMEM_FIN>>>(w, ew);
    k_combine<<<16, 256>>>(w, out);
}

// round 15
// speedup vs baseline: 1.0748x; 1.0748x over previous
#include <cuda_runtime.h>
#include <cuda_fp16.h>
#include <math.h>
#include <stdint.h>

#define NPTS 4096
#define DS 48
#define DA 16
#define DF 64
#define TB 128
#define NTILE (NPTS / TB)      /* 32 */
#define NB1 2048               /* coarse bins over [0,16] */
#define SC1 128.0f             /* NB1/16 */
#define NBF 4096               /* fine bins in refine pass */
#define WIN 2                  /* coarse window half-width (bins) */

// ---------------- device scratch ----------------
__device__ __half g_hA[(size_t)NPTS * DF];
__device__ __half g_hB[(size_t)NPTS * DF];
__device__ float  g_x2[NPTS];
__device__ float  g_y2[NPTS];
__device__ float  g_hcoarse[2 * NB1];
__device__ float  g_hfine[2 * NBF];
__device__ double g_below[2];
__device__ double g_scal[8];   // 0 Wsum,1 EWsum,2/3 lo/width ae,4/5 lo/width ee,6 g1,7 g2
__device__ float  g_Sae[NPTS];
__device__ float  g_Saa[NPTS];

// ---------------- mma / ldmatrix helpers (fp16 in, fp32 accum) ----------------
#define MMA_AB(d, A, b0, b1)                                                \
    asm volatile(                                                           \
        "mma.sync.aligned.m16n8k16.row.col.f32.f16.f16.f32 "                \
        "{%0,%1,%2,%3}, {%4,%5,%6,%7}, {%8,%9}, {%0,%1,%2,%3};"             \
        : "+f"((d)[0]), "+f"((d)[1]), "+f"((d)[2]), "+f"((d)[3])            \
        : "r"((A)[0]), "r"((A)[1]), "r"((A)[2]), "r"((A)[3]), "r"(b0), "r"(b1))

__device__ __forceinline__ void ldsm4(uint32_t a, uint32_t d[4]) {
    asm volatile("ldmatrix.sync.aligned.m8n8.x4.shared.b16 {%0,%1,%2,%3}, [%4];"
                 : "=r"(d[0]), "=r"(d[1]), "=r"(d[2]), "=r"(d[3]) : "r"(a));
}

#define SWO(r, kc) ((uint32_t)(r) * 128u + (((uint32_t)(kc)) ^ (((uint32_t)(r) & 7u) << 4)))
#define TILE_BYTES 16384

// ---------------- staging: global (row-major 128B rows) -> swizzled smem tile ----------------
__device__ __forceinline__ void stage_one(char* dst, const __half* src,
                                          int row0, int rstride, int tid, int nrows) {
    const uint4* p = (const uint4*)src;
    for (int idx = tid; idx < nrows * 8; idx += 256) {
        int r = idx >> 3, c = idx & 7;
        uint32_t off = (uint32_t)r * 128u + (((uint32_t)c * 16u) ^ (((uint32_t)r & 7u) << 4));
        *(uint4*)(dst + off) = p[(size_t)(row0 + r * rstride) * 8 + c];
    }
}

// ---------------- mainloop: single-product fp16 mma ----------------
template <int MF>
__device__ __forceinline__ void mma_loop(uint32_t sA, uint32_t sB,
                                         int tid, float acc[4][4][4]) {
    const int lane = tid & 31, warp = tid >> 5;
    const int wr = warp >> 2, wc = warp & 3;

    #pragma unroll
    for (int mf = 0; mf < MF; mf++)
        #pragma unroll
        for (int nf = 0; nf < 4; nf++)
            #pragma unroll
            for (int u = 0; u < 4; u++) acc[mf][nf][u] = 0.f;

    const int aRow = lane & 15;
    const int aKc  = (lane >> 4) << 4;
    const int bRow = ((lane & 16) >> 1) + (lane & 7);
    const int bKc  = (lane & 8) ? 16 : 0;

    #pragma unroll
    for (int ks = 0; ks < 4; ks++) {
        const int kc0 = ks * 32;
        uint32_t BH[2][4];
        #pragma unroll
        for (int p = 0; p < 2; p++) {
            uint32_t off = SWO(wc * 32 + p * 16 + bRow, kc0 + bKc);
            ldsm4(sB + off, BH[p]);
        }
        #pragma unroll
        for (int mf = 0; mf < MF; mf++) {
            uint32_t off = SWO(wr * (MF * 16) + mf * 16 + aRow, kc0 + aKc);
            uint32_t AH[4];
            ldsm4(sA + off, AH);
            #pragma unroll
            for (int p = 0; p < 2; p++) {
                MMA_AB(acc[mf][2 * p],     AH, BH[p][0], BH[p][1]);
                MMA_AB(acc[mf][2 * p + 1], AH, BH[p][2], BH[p][3]);
            }
        }
    }
}

// ---------------- convert inputs to fp16 + row norms + zero accumulators ----------------
__global__ void k_cvt(const float* __restrict__ ss, const float* __restrict__ aa_,
                      const float* __restrict__ es, const float* __restrict__ ea) {
    __shared__ float cvt_part[8];
    int tid = threadIdx.x;
    int gid = blockIdx.x * 256 + tid;
    if (gid < 2 * NB1) g_hcoarse[gid] = 0.f;
    if (gid < 2 * NBF) g_hfine[gid]   = 0.f;
    if (gid < NPTS)  { g_Saa[gid] = 0.f; g_Sae[gid] = 0.f; }
    if (gid < 2)       g_below[gid]   = 0.0;

    int gr = blockIdx.x * 4 + (tid >> 6);
    int k  = tid & 63;
    bool isA = (gr < NPTS);
    int r = isA ? gr : gr - NPTS;
    const float* sp = isA ? ss : es;
    const float* ap = isA ? aa_ : ea;
    __half* hp = isA ? g_hA : g_hB;

    float v = (k < DS) ? sp[(size_t)r * DS + k] : ap[(size_t)r * DA + (k - DS)];
    hp[(size_t)r * DF + k] = __float2half(v);

    float sq = v * v;
    #pragma unroll
    for (int off = 16; off; off >>= 1) sq += __shfl_xor_sync(0xFFFFFFFF, sq, off);
    if ((tid & 31) == 0) cvt_part[tid >> 5] = sq;
    __syncthreads();
    if ((tid & 63) == 0) {
        float s = cvt_part[(tid >> 5)] + cvt_part[(tid >> 5) + 1];
        if (isA) g_x2[r] = s; else g_y2[r] = s;
    }
}

// ---------------- sampled coarse hist via fp16 MMA, M=64 tiles ----------------
#define HOF_X2    0
#define HOF_WX    256
#define HOF_Y2    512
#define HOF_WY    1024
#define HOF_HIST  1536
#define HOF_TILES 17920
#define SMEM_HS   (HOF_TILES + 8192 + 16384)   /* 42496 */

__global__ void __launch_bounds__(256) k_hist_sampled(
    const float* __restrict__ w, const float* __restrict__ ew)
{
    extern __shared__ __align__(128) char smem[];
    int tid = threadIdx.x;
    bool ae = (blockIdx.z == 0);
    int col0 = blockIdx.x * TB;
    int sbase = blockIdx.y * 64;

    const __half* Ah = ae ? g_hA : g_hB;
    const float* x2p = ae ? g_x2 : g_y2;
    const float* wxp = ae ? w : ew;

    float* shh = (float*)(smem + HOF_HIST);
    for (int i = tid; i < 2 * NB1; i += 256) shh[i] = 0.f;

    stage_one(smem + HOF_TILES,        Ah,   sbase * 16, 16, tid, 64);
    stage_one(smem + HOF_TILES + 8192, g_hB, col0,       1,  tid, 128);
    if (tid < 64) {
        ((float*)(smem + HOF_X2))[tid] = x2p[(sbase + tid) * 16];
        ((float*)(smem + HOF_WX))[tid] = wxp[(sbase + tid) * 16];
    }
    if (tid < TB) {
        ((float*)(smem + HOF_Y2))[tid] = g_y2[col0 + tid];
        ((float*)(smem + HOF_WY))[tid] = ew[col0 + tid];
    }
    __syncthreads();

    uint32_t sT = (uint32_t)__cvta_generic_to_shared(smem) + HOF_TILES;
    float acc[4][4][4];
    mma_loop<2>(sT, sT + 8192, tid, acc);

    const int lane = tid & 31, warp = tid >> 5;
    const int wr = warp >> 2, wc = warp & 3;
    const int g = lane >> 2, t = lane & 3;
    const float* x2s = (const float*)(smem + HOF_X2);
    const float* wxs = (const float*)(smem + HOF_WX);
    const float* y2s = (const float*)(smem + HOF_Y2);
    const float* wys = (const float*)(smem + HOF_WY);
    float* myh = shh + (warp & 1) * NB1;

    #pragma unroll
    for (int mf = 0; mf < 2; mf++) {
        int r0 = wr * 32 + mf * 16 + g;
        float x0 = x2s[r0], x1 = x2s[r0 + 8];
        float wx0 = wxs[r0], wx1 = wxs[r0 + 8];
        #pragma unroll
        for (int nf = 0; nf < 4; nf++) {
            int c0 = wc * 32 + nf * 8 + 2 * t;
            float y0 = y2s[c0], y1 = y2s[c0 + 1];
            float wy0 = wys[c0], wy1 = wys[c0 + 1];
            float d00 = fmaxf(x0 + y0 - 2.f * acc[mf][nf][0], 0.f) * (1.f / DF);
            float d01 = fmaxf(x0 + y1 - 2.f * acc[mf][nf][1], 0.f) * (1.f / DF);
            float d10 = fmaxf(x1 + y0 - 2.f * acc[mf][nf][2], 0.f) * (1.f / DF);
            float d11 = fmaxf(x1 + y1 - 2.f * acc[mf][nf][3], 0.f) * (1.f / DF);
            atomicAdd(&myh[min((int)(d00 * SC1), NB1 - 1)], wx0 * wy0);
            atomicAdd(&myh[min((int)(d01 * SC1), NB1 - 1)], wx0 * wy1);
            atomicAdd(&myh[min((int)(d10 * SC1), NB1 - 1)], wx1 * wy0);
            atomicAdd(&myh[min((int)(d11 * SC1), NB1 - 1)], wx1 * wy1);
        }
    }
    __syncthreads();
    float* hist = g_hcoarse + (ae ? 0 : NB1);
    for (int i = tid; i < NB1; i += 256) {
        float v = shh[i] + shh[i + NB1];
        if (v != 0.f) atomicAdd(&hist[i], v);
    }
}

// ---------------- scan coarse hist -> window (±WIN bins); also weight sums ----------------
__global__ void k_scan0(const float* __restrict__ w, const float* __restrict__ ew) {
    int which = blockIdx.x;
    int tid = threadIdx.x;
    __shared__ double part[256];

    {
        const float* src = which ? ew : w;
        double s = 0.0;
        for (int i = tid; i < NPTS; i += 256) s += src[i];
        part[tid] = s; __syncthreads();
        for (int off = 128; off; off >>= 1) {
            if (tid < off) part[tid] += part[tid + off];
            __syncthreads();
        }
        if (tid == 0) g_scal[which] = part[0];
        __syncthreads();
    }

    const float* h = g_hcoarse + which * NB1;
    double loc[8], s = 0.0;
    #pragma unroll
    for (int i = 0; i < 8; i++) { loc[i] = h[tid * 8 + i]; s += loc[i]; }
    part[tid] = s; __syncthreads();
    for (int off = 1; off < 256; off <<= 1) {
        double v = (tid >= off) ? part[tid - off] : 0.0;
        __syncthreads();
        part[tid] += v;
        __syncthreads();
    }
    double T = 0.5 * part[255];
    double c = tid ? part[tid - 1] : 0.0;
    int b = -1;
    #pragma unroll
    for (int i = 0; i < 8; i++) {
        double nc = c + loc[i];
        if (b < 0 && c < T && nc >= T) b = tid * 8 + i;
        c = nc;
    }
    if (b >= 0) {
        int blo = b > WIN ? b - WIN : 0;
        int bhi = b + WIN + 1 > NB1 ? NB1 : b + WIN + 1;
        g_scal[2 + 2 * which] = blo * (16.0 / NB1);
        g_scal[3 + 2 * which] = (bhi - blo) * (16.0 / NB1);
    }
}

// ---------------- fused refine: shared B col tile, phases ae (A=hA) / ee (A=hB) ------------
#define ROF_X2AE  0
#define ROF_X2EE  512
#define ROF_Y2    1024
#define ROF_WXAE  1536
#define ROF_WXEE  2048
#define ROF_WY    2560
#define ROF_HIST  3072                       /* NBF*4 = 16384 */
#define ROF_TILES 19456
#define SMEM_RF   (ROF_TILES + 3 * TILE_BYTES)   /* 68608 */

__global__ void __launch_bounds__(256) k_refine_fused(
    const float* __restrict__ w, const float* __restrict__ ew)
{
    extern __shared__ __align__(128) char smem[];
    __shared__ float red[256];
    int tid = threadIdx.x;
    int row0 = blockIdx.y * TB, col0 = blockIdx.x * TB;

    float* shh = (float*)(smem + ROF_HIST);
    for (int i = tid; i < NBF; i += 256) shh[i] = 0.f;

    stage_one(smem + ROF_TILES,                  g_hA, row0, 1, tid, 128);  // A_ae
    stage_one(smem + ROF_TILES + TILE_BYTES,     g_hB, row0, 1, tid, 128);  // A_ee
    stage_one(smem + ROF_TILES + 2 * TILE_BYTES, g_hB, col0, 1, tid, 128);  // B (shared)
    if (tid < TB) {
        ((float*)(smem + ROF_X2AE))[tid] = g_x2[row0 + tid];
        ((float*)(smem + ROF_X2EE))[tid] = g_y2[row0 + tid];
        ((float*)(smem + ROF_Y2))[tid]   = g_y2[col0 + tid];
        ((float*)(smem + ROF_WXAE))[tid] = w[row0 + tid];
        ((float*)(smem + ROF_WXEE))[tid] = ew[row0 + tid];
        ((float*)(smem + ROF_WY))[tid]   = ew[col0 + tid];
    }
    __syncthreads();

    uint32_t sT = (uint32_t)__cvta_generic_to_shared(smem) + ROF_TILES;
    const int lane = tid & 31, warp = tid >> 5;
    const int wr = warp >> 2, wc = warp & 3;
    const int g = lane >> 2, t = lane & 3;
    const float* y2s = (const float*)(smem + ROF_Y2);
    const float* wys = (const float*)(smem + ROF_WY);

    #pragma unroll
    for (int phase = 0; phase < 2; phase++) {
        int which = phase;
        const float* x2s = (const float*)(smem + (phase ? ROF_X2EE : ROF_X2AE));
        const float* wxs = (const float*)(smem + (phase ? ROF_WXEE : ROF_WXAE));
        float lo    = (float)g_scal[2 + 2 * which];
        float scale = (float)((double)NBF / g_scal[3 + 2 * which]);

        float acc[4][4][4];
        mma_loop<4>(sT + phase * TILE_BYTES, sT + 2 * TILE_BYTES, tid, acc);

        float bacc = 0.f;
        #pragma unroll
        for (int mf = 0; mf < 4; mf++) {
            int r0 = wr * 64 + mf * 16 + g;
            float x0 = x2s[r0], x1 = x2s[r0 + 8];
            float wx0 = wxs[r0], wx1 = wxs[r0 + 8];
            #pragma unroll
            for (int nf = 0; nf < 4; nf++) {
                int c0 = wc * 32 + nf * 8 + 2 * t;
                float y0 = y2s[c0], y1 = y2s[c0 + 1];
                float wy0 = wys[c0], wy1 = wys[c0 + 1];
                float dd[4], wt[4];
                dd[0] = fmaxf(x0 + y0 - 2.f * acc[mf][nf][0], 0.f) * (1.f / DF); wt[0] = wx0 * wy0;
                dd[1] = fmaxf(x0 + y1 - 2.f * acc[mf][nf][1], 0.f) * (1.f / DF); wt[1] = wx0 * wy1;
                dd[2] = fmaxf(x1 + y0 - 2.f * acc[mf][nf][2], 0.f) * (1.f / DF); wt[2] = wx1 * wy0;
                dd[3] = fmaxf(x1 + y1 - 2.f * acc[mf][nf][3], 0.f) * (1.f / DF); wt[3] = wx1 * wy1;
                #pragma unroll
                for (int u = 0; u < 4; u++) {
                    if (dd[u] < lo) bacc += wt[u];
                    else {
                        int b = (int)((dd[u] - lo) * scale);
                        if (b < NBF) atomicAdd(&shh[b], wt[u]);
                    }
                }
            }
        }
        red[tid] = bacc; __syncthreads();
        for (int off = 128; off; off >>= 1) {
            if (tid < off) red[tid] += red[tid + off];
            __syncthreads();
        }
        if (tid == 0) atomicAdd(&g_below[which], (double)red[0]);
        float* hist = g_hfine + which * NBF;
        for (int i = tid; i < NBF; i += 256) {
            float v = shh[i];
            if (v != 0.f) atomicAdd(&hist[i], v);
            if (phase == 0) shh[i] = 0.f;
        }
        __syncthreads();
    }
}

// ---------------- scan fine hist -> g (512 threads x 8 bins) ----------------
__global__ void k_scanF() {
    int which = blockIdx.x;
    const float* h = g_hfine + which * NBF;
    __shared__ double part[512];
    int tid = threadIdx.x;
    double loc[8], s = 0.0;
    #pragma unroll
    for (int i = 0; i < 8; i++) { loc[i] = h[tid * 8 + i]; s += loc[i]; }
    part[tid] = s; __syncthreads();
    for (int off = 1; off < 512; off <<= 1) {
        double v = (tid >= off) ? part[tid - off] : 0.0;
        __syncthreads();
        part[tid] += v;
        __syncthreads();
    }
    double Wtot = (which == 0) ? g_scal[0] * g_scal[1] : g_scal[1] * g_scal[1];
    double T = 0.5 * Wtot - g_below[which];
    double lo = g_scal[2 + 2 * which], wdt = g_scal[3 + 2 * which];
    double c = tid ? part[tid - 1] : 0.0;
    int b = -1;
    #pragma unroll
    for (int i = 0; i < 8; i++) {
        double nc = c + loc[i];
        if (b < 0 && c < T && nc >= T) b = tid * 8 + i;
        c = nc;
    }
    if (tid == 0 && T <= 0.0) b = 0;
    if (tid == 511 && T > 0.0 && part[511] < T && b < 0) b = NBF - 1;
    if (b >= 0) {
        double tt = lo + (b + 0.5) * (wdt / NBF);
        g_scal[6 + which] = 1.0 / (tt + 1e-8);
    }
}

// ---------------- fused final: shared A row tile, phases ae (B=hB) / aa (B=hA) ------------
#define FOF_X2    0
#define FOF_Y2AE  512
#define FOF_Y2AA  1024
#define FOF_WAE   1536
#define FOF_WAA   2048
#define FOF_RS    2560
#define FOF_TILES 3072
#define SMEM_FIN  (FOF_TILES + 3 * TILE_BYTES)   /* 52224 */

__global__ void __launch_bounds__(256) k_final_fused(
    const float* __restrict__ w, const float* __restrict__ ew)
{
    extern __shared__ __align__(128) char smem[];
    int tid = threadIdx.x;
    int row0 = blockIdx.y * TB, col0 = blockIdx.x * TB;

    stage_one(smem + FOF_TILES,                  g_hA, row0, 1, tid, 128);
    stage_one(smem + FOF_TILES + TILE_BYTES,     g_hB, col0, 1, tid, 128);
    stage_one(smem + FOF_TILES + 2 * TILE_BYTES, g_hA, col0, 1, tid, 128);
    if (tid < TB) {
        ((float*)(smem + FOF_X2))[tid]   = g_x2[row0 + tid];
        ((float*)(smem + FOF_Y2AE))[tid] = g_y2[col0 + tid];
        ((float*)(smem + FOF_Y2AA))[tid] = g_x2[col0 + tid];
        ((float*)(smem + FOF_WAE))[tid]  = ew[col0 + tid];
        ((float*)(smem + FOF_WAA))[tid]  = w[col0 + tid];
        ((float*)(smem + FOF_RS))[tid]   = 0.f;
    }
    __syncthreads();

    uint32_t sT = (uint32_t)__cvta_generic_to_shared(smem) + FOF_TILES;
    const int lane = tid & 31, warp = tid >> 5;
    const int wr = warp >> 2, wc = warp & 3;
    const int g = lane >> 2, t = lane & 3;
    const float* x2s = (const float*)(smem + FOF_X2);
    float* rowsum = (float*)(smem + FOF_RS);

    float G1 = (float)g_scal[6], G2 = (float)g_scal[7];

    #pragma unroll
    for (int phase = 0; phase < 2; phase++) {
        const float* y2s = (const float*)(smem + (phase ? FOF_Y2AA : FOF_Y2AE));
        const float* ws  = (const float*)(smem + (phase ? FOF_WAA : FOF_WAE));

        float acc[4][4][4];
        mma_loop<4>(sT, sT + (1 + phase) * TILE_BYTES, tid, acc);

        #pragma unroll
        for (int mf = 0; mf < 4; mf++) {
            int r0 = wr * 64 + mf * 16 + g;
            float x0 = x2s[r0], x1 = x2s[r0 + 8];
            float p0 = 0.f, p1 = 0.f;
            #pragma unroll
            for (int nf = 0; nf < 4; nf++) {
                int c0 = wc * 32 + nf * 8 + 2 * t;
                float y0 = y2s[c0], y1 = y2s[c0 + 1];
                float w0 = ws[c0],  w1 = ws[c0 + 1];
                float d00 = fmaxf(x0 + y0 - 2.f * acc[mf][nf][0], 0.f) * (1.f / DF);
                float d01 = fmaxf(x0 + y1 - 2.f * acc[mf][nf][1], 0.f) * (1.f / DF);
                float d10 = fmaxf(x1 + y0 - 2.f * acc[mf][nf][2], 0.f) * (1.f / DF);
                float d11 = fmaxf(x1 + y1 - 2.f * acc[mf][nf][3], 0.f) * (1.f / DF);
                p0 += (__expf(-G1 * d00) + __expf(-G2 * d00)) * w0
                    + (__expf(-G1 * d01) + __expf(-G2 * d01)) * w1;
                p1 += (__expf(-G1 * d10) + __expf(-G2 * d10)) * w0
                    + (__expf(-G1 * d11) + __expf(-G2 * d11)) * w1;
            }
            atomicAdd(&rowsum[r0], p0);
            atomicAdd(&rowsum[r0 + 8], p1);
        }
        __syncthreads();
        if (tid < TB) {
            float* Sout = phase ? g_Saa : g_Sae;
            atomicAdd(&Sout[row0 + tid], rowsum[tid]);
            rowsum[tid] = 0.f;
        }
        __syncthreads();
    }
}

// ---------------- final combine ----------------
__global__ void k_combine(const float* __restrict__ w, float* __restrict__ out) {
    int i = blockIdx.x * blockDim.x + threadIdx.x;
    if (i < NPTS) {
        float Ws  = (float)g_scal[0];
        float EWs = (float)g_scal[1];
        out[i] = (w[i] / Ws) * (g_Sae[i] / EWs - g_Saa[i] / Ws);
    }
}

// ---------------- host launcher ----------------
extern "C" void kernel_launch(void* const* d_in, const int* in_sizes, int n_in,
                              void* d_out, int out_size)
{
    const float* state   = (const float*)d_in[0];
    const float* action  = (const float*)d_in[1];
    const float* estate  = (const float*)d_in[2];
    const float* eaction = (const float*)d_in[3];
    const float* w       = (const float*)d_in[4];
    const float* ew      = (const float*)d_in[5];
    float* out = (float*)d_out;

    cudaFuncSetAttribute(k_hist_sampled, cudaFuncAttributeMaxDynamicSharedMemorySize, SMEM_HS);
    cudaFuncSetAttribute(k_refine_fused, cudaFuncAttributeMaxDynamicSharedMemorySize, SMEM_RF);
    cudaFuncSetAttribute(k_final_fused,  cudaFuncAttributeMaxDynamicSharedMemorySize, SMEM_FIN);

    dim3 ghs(NTILE, 4, 2);
    dim3 gtile(NTILE, NTILE);

    k_cvt<<<2048, 256>>>(state, action, estate, eaction);
    k_hist_sampled<<<ghs, 256, SMEM_HS>>>(w, ew);
    k_scan0<<<2, 256>>>(w, ew);
    k_refine_fused<<<gtile, 256, SMEM_RF>>>(w, ew);
    k_scanF<<<2, 512>>>();
    k_final_fused<<<gtile, 256, SMEM_FIN>>>(w, ew);
    k_combine<<<16, 256>>>(w, out);
}

// round 16
// speedup vs baseline: 1.1233x; 1.0451x over previous
#include <cuda_runtime.h>
#include <cuda_fp16.h>
#include <math.h>
#include <stdint.h>

#define NPTS 4096
#define DS 48
#define DA 16
#define DF 64
#define TB 128
#define NTILE (NPTS / TB)      /* 32 */
#define NB1 2048               /* coarse bins over [0,16] */
#define SC1 128.0f             /* NB1/16 */
#define NBF 4096               /* fine bins in refine pass */
#define WIN 2                  /* coarse window half-width (bins) */

// ---------------- device scratch ----------------
__device__ __half g_hA[(size_t)NPTS * DF];
__device__ __half g_hB[(size_t)NPTS * DF];
__device__ float  g_x2[NPTS];
__device__ float  g_y2[NPTS];
__device__ float  g_hcoarse[2 * NB1];
__device__ float  g_hfine[2 * NBF];
__device__ double g_below[2];
__device__ double g_scal[8];   // 0 Wsum,1 EWsum,2/3 lo/width ae,4/5 lo/width ee,6 g1,7 g2
__device__ float  g_Sae[NPTS];
__device__ float  g_Saa[NPTS];

// ---------------- mma / ldmatrix helpers (fp16 in, fp32 accum) ----------------
#define MMA_AB(d, A, b0, b1)                                                \
    asm volatile(                                                           \
        "mma.sync.aligned.m16n8k16.row.col.f32.f16.f16.f32 "                \
        "{%0,%1,%2,%3}, {%4,%5,%6,%7}, {%8,%9}, {%0,%1,%2,%3};"             \
        : "+f"((d)[0]), "+f"((d)[1]), "+f"((d)[2]), "+f"((d)[3])            \
        : "r"((A)[0]), "r"((A)[1]), "r"((A)[2]), "r"((A)[3]), "r"(b0), "r"(b1))

__device__ __forceinline__ void ldsm4(uint32_t a, uint32_t d[4]) {
    asm volatile("ldmatrix.sync.aligned.m8n8.x4.shared.b16 {%0,%1,%2,%3}, [%4];"
                 : "=r"(d[0]), "=r"(d[1]), "=r"(d[2]), "=r"(d[3]) : "r"(a));
}

#define SWO(r, kc) ((uint32_t)(r) * 128u + (((uint32_t)(kc)) ^ (((uint32_t)(r) & 7u) << 4)))
#define TILE_BYTES 16384

// ---------------- staging: global (row-major 128B rows) -> swizzled smem tile ----------------
__device__ __forceinline__ void stage_one(char* dst, const __half* src,
                                          int row0, int rstride, int tid, int nrows) {
    const uint4* p = (const uint4*)src;
    for (int idx = tid; idx < nrows * 8; idx += 256) {
        int r = idx >> 3, c = idx & 7;
        uint32_t off = (uint32_t)r * 128u + (((uint32_t)c * 16u) ^ (((uint32_t)r & 7u) << 4));
        *(uint4*)(dst + off) = p[(size_t)(row0 + r * rstride) * 8 + c];
    }
}

// ---------------- mainloop: single-product fp16 mma ----------------
template <int MF>
__device__ __forceinline__ void mma_loop(uint32_t sA, uint32_t sB,
                                         int tid, float acc[4][4][4]) {
    const int lane = tid & 31, warp = tid >> 5;
    const int wr = warp >> 2, wc = warp & 3;

    #pragma unroll
    for (int mf = 0; mf < MF; mf++)
        #pragma unroll
        for (int nf = 0; nf < 4; nf++)
            #pragma unroll
            for (int u = 0; u < 4; u++) acc[mf][nf][u] = 0.f;

    const int aRow = lane & 15;
    const int aKc  = (lane >> 4) << 4;
    const int bRow = ((lane & 16) >> 1) + (lane & 7);
    const int bKc  = (lane & 8) ? 16 : 0;

    #pragma unroll
    for (int ks = 0; ks < 4; ks++) {
        const int kc0 = ks * 32;
        uint32_t BH[2][4];
        #pragma unroll
        for (int p = 0; p < 2; p++) {
            uint32_t off = SWO(wc * 32 + p * 16 + bRow, kc0 + bKc);
            ldsm4(sB + off, BH[p]);
        }
        #pragma unroll
        for (int mf = 0; mf < MF; mf++) {
            uint32_t off = SWO(wr * (MF * 16) + mf * 16 + aRow, kc0 + aKc);
            uint32_t AH[4];
            ldsm4(sA + off, AH);
            #pragma unroll
            for (int p = 0; p < 2; p++) {
                MMA_AB(acc[mf][2 * p],     AH, BH[p][0], BH[p][1]);
                MMA_AB(acc[mf][2 * p + 1], AH, BH[p][2], BH[p][3]);
            }
        }
    }
}

// ---------------- convert inputs to fp16 + row norms + zero accumulators ----------------
__global__ void k_cvt(const float* __restrict__ ss, const float* __restrict__ aa_,
                      const float* __restrict__ es, const float* __restrict__ ea) {
    __shared__ float cvt_part[8];
    int tid = threadIdx.x;
    int gid = blockIdx.x * 256 + tid;
    if (gid < 2 * NB1) g_hcoarse[gid] = 0.f;
    if (gid < 2 * NBF) g_hfine[gid]   = 0.f;
    if (gid < NPTS)  { g_Saa[gid] = 0.f; g_Sae[gid] = 0.f; }
    if (gid < 2)       g_below[gid]   = 0.0;

    int gr = blockIdx.x * 4 + (tid >> 6);
    int k  = tid & 63;
    bool isA = (gr < NPTS);
    int r = isA ? gr : gr - NPTS;
    const float* sp = isA ? ss : es;
    const float* ap = isA ? aa_ : ea;
    __half* hp = isA ? g_hA : g_hB;

    float v = (k < DS) ? sp[(size_t)r * DS + k] : ap[(size_t)r * DA + (k - DS)];
    hp[(size_t)r * DF + k] = __float2half(v);

    float sq = v * v;
    #pragma unroll
    for (int off = 16; off; off >>= 1) sq += __shfl_xor_sync(0xFFFFFFFF, sq, off);
    if ((tid & 31) == 0) cvt_part[tid >> 5] = sq;
    __syncthreads();
    if ((tid & 63) == 0) {
        float s = cvt_part[(tid >> 5)] + cvt_part[(tid >> 5) + 1];
        if (isA) g_x2[r] = s; else g_y2[r] = s;
    }
}

// ---------------- sampled coarse hist via fp16 MMA, M=64 tiles ----------------
#define HOF_X2    0
#define HOF_WX    256
#define HOF_Y2    512
#define HOF_WY    1024
#define HOF_HIST  1536
#define HOF_TILES 17920
#define SMEM_HS   (HOF_TILES + 8192 + 16384)   /* 42496 */

__global__ void __launch_bounds__(256) k_hist_sampled(
    const float* __restrict__ w, const float* __restrict__ ew)
{
    extern __shared__ __align__(128) char smem[];
    int tid = threadIdx.x;
    bool ae = (blockIdx.z == 0);
    int col0 = blockIdx.x * TB;
    int sbase = blockIdx.y * 64;

    const __half* Ah = ae ? g_hA : g_hB;
    const float* x2p = ae ? g_x2 : g_y2;
    const float* wxp = ae ? w : ew;

    float* shh = (float*)(smem + HOF_HIST);
    for (int i = tid; i < 2 * NB1; i += 256) shh[i] = 0.f;

    stage_one(smem + HOF_TILES,        Ah,   sbase * 16, 16, tid, 64);
    stage_one(smem + HOF_TILES + 8192, g_hB, col0,       1,  tid, 128);
    if (tid < 64) {
        ((float*)(smem + HOF_X2))[tid] = x2p[(sbase + tid) * 16];
        ((float*)(smem + HOF_WX))[tid] = wxp[(sbase + tid) * 16];
    }
    if (tid < TB) {
        ((float*)(smem + HOF_Y2))[tid] = g_y2[col0 + tid];
        ((float*)(smem + HOF_WY))[tid] = ew[col0 + tid];
    }
    __syncthreads();

    uint32_t sT = (uint32_t)__cvta_generic_to_shared(smem) + HOF_TILES;
    float acc[4][4][4];
    mma_loop<2>(sT, sT + 8192, tid, acc);

    const int lane = tid & 31, warp = tid >> 5;
    const int wr = warp >> 2, wc = warp & 3;
    const int g = lane >> 2, t = lane & 3;
    const float* x2s = (const float*)(smem + HOF_X2);
    const float* wxs = (const float*)(smem + HOF_WX);
    const float* y2s = (const float*)(smem + HOF_Y2);
    const float* wys = (const float*)(smem + HOF_WY);
    float* myh = shh + (warp & 1) * NB1;

    #pragma unroll
    for (int mf = 0; mf < 2; mf++) {
        int r0 = wr * 32 + mf * 16 + g;
        float x0 = x2s[r0], x1 = x2s[r0 + 8];
        float wx0 = wxs[r0], wx1 = wxs[r0 + 8];
        #pragma unroll
        for (int nf = 0; nf < 4; nf++) {
            int c0 = wc * 32 + nf * 8 + 2 * t;
            float y0 = y2s[c0], y1 = y2s[c0 + 1];
            float wy0 = wys[c0], wy1 = wys[c0 + 1];
            float d00 = fmaxf(x0 + y0 - 2.f * acc[mf][nf][0], 0.f) * (1.f / DF);
            float d01 = fmaxf(x0 + y1 - 2.f * acc[mf][nf][1], 0.f) * (1.f / DF);
            float d10 = fmaxf(x1 + y0 - 2.f * acc[mf][nf][2], 0.f) * (1.f / DF);
            float d11 = fmaxf(x1 + y1 - 2.f * acc[mf][nf][3], 0.f) * (1.f / DF);
            atomicAdd(&myh[min((int)(d00 * SC1), NB1 - 1)], wx0 * wy0);
            atomicAdd(&myh[min((int)(d01 * SC1), NB1 - 1)], wx0 * wy1);
            atomicAdd(&myh[min((int)(d10 * SC1), NB1 - 1)], wx1 * wy0);
            atomicAdd(&myh[min((int)(d11 * SC1), NB1 - 1)], wx1 * wy1);
        }
    }
    __syncthreads();
    float* hist = g_hcoarse + (ae ? 0 : NB1);
    for (int i = tid; i < NB1; i += 256) {
        float v = shh[i] + shh[i + NB1];
        if (v != 0.f) atomicAdd(&hist[i], v);
    }
}

// ---------------- scan coarse hist -> window (±WIN bins); also weight sums ----------------
__global__ void k_scan0(const float* __restrict__ w, const float* __restrict__ ew) {
    int which = blockIdx.x;
    int tid = threadIdx.x;
    __shared__ double part[256];

    {
        const float* src = which ? ew : w;
        double s = 0.0;
        for (int i = tid; i < NPTS; i += 256) s += src[i];
        part[tid] = s; __syncthreads();
        for (int off = 128; off; off >>= 1) {
            if (tid < off) part[tid] += part[tid + off];
            __syncthreads();
        }
        if (tid == 0) g_scal[which] = part[0];
        __syncthreads();
    }

    const float* h = g_hcoarse + which * NB1;
    double loc[8], s = 0.0;
    #pragma unroll
    for (int i = 0; i < 8; i++) { loc[i] = h[tid * 8 + i]; s += loc[i]; }
    part[tid] = s; __syncthreads();
    for (int off = 1; off < 256; off <<= 1) {
        double v = (tid >= off) ? part[tid - off] : 0.0;
        __syncthreads();
        part[tid] += v;
        __syncthreads();
    }
    double T = 0.5 * part[255];
    double c = tid ? part[tid - 1] : 0.0;
    int b = -1;
    #pragma unroll
    for (int i = 0; i < 8; i++) {
        double nc = c + loc[i];
        if (b < 0 && c < T && nc >= T) b = tid * 8 + i;
        c = nc;
    }
    if (b >= 0) {
        int blo = b > WIN ? b - WIN : 0;
        int bhi = b + WIN + 1 > NB1 ? NB1 : b + WIN + 1;
        g_scal[2 + 2 * which] = blo * (16.0 / NB1);
        g_scal[3 + 2 * which] = (bhi - blo) * (16.0 / NB1);
    }
}

// ---------------- fused refine: raw-space lean epilogue ----------------
#define ROF_X2AE  0
#define ROF_X2EE  512
#define ROF_Y2    1024
#define ROF_WXAE  1536
#define ROF_WXEE  2048
#define ROF_WY    2560
#define ROF_HIST  3072                       /* NBF*4 = 16384 */
#define ROF_TILES 19456
#define SMEM_RF   (ROF_TILES + 3 * TILE_BYTES)   /* 68608 */

__global__ void __launch_bounds__(256) k_refine_fused(
    const float* __restrict__ w, const float* __restrict__ ew)
{
    extern __shared__ __align__(128) char smem[];
    __shared__ float red[256];
    int tid = threadIdx.x;
    int row0 = blockIdx.y * TB, col0 = blockIdx.x * TB;

    float* shh = (float*)(smem + ROF_HIST);
    for (int i = tid; i < NBF; i += 256) shh[i] = 0.f;

    stage_one(smem + ROF_TILES,                  g_hA, row0, 1, tid, 128);  // A_ae
    stage_one(smem + ROF_TILES + TILE_BYTES,     g_hB, row0, 1, tid, 128);  // A_ee
    stage_one(smem + ROF_TILES + 2 * TILE_BYTES, g_hB, col0, 1, tid, 128);  // B (shared)
    if (tid < TB) {
        ((float*)(smem + ROF_X2AE))[tid] = g_x2[row0 + tid];
        ((float*)(smem + ROF_X2EE))[tid] = g_y2[row0 + tid];
        ((float*)(smem + ROF_Y2))[tid]   = g_y2[col0 + tid];
        ((float*)(smem + ROF_WXAE))[tid] = w[row0 + tid];
        ((float*)(smem + ROF_WXEE))[tid] = ew[row0 + tid];
        ((float*)(smem + ROF_WY))[tid]   = ew[col0 + tid];
    }
    __syncthreads();

    uint32_t sT = (uint32_t)__cvta_generic_to_shared(smem) + ROF_TILES;
    const int lane = tid & 31, warp = tid >> 5;
    const int wr = warp >> 2, wc = warp & 3;
    const int g = lane >> 2, t = lane & 3;
    const float* y2s = (const float*)(smem + ROF_Y2);
    const float* wys = (const float*)(smem + ROF_WY);

    #pragma unroll
    for (int phase = 0; phase < 2; phase++) {
        int which = phase;
        const float* x2s = (const float*)(smem + (phase ? ROF_X2EE : ROF_X2AE));
        const float* wxs = (const float*)(smem + (phase ? ROF_WXEE : ROF_WXAE));
        // raw-space thresholds: raw = x2 + y2 - 2*dot = d * 64
        float lo64    = (float)(g_scal[2 + 2 * which] * 64.0);
        float hi64    = (float)((g_scal[2 + 2 * which] + g_scal[3 + 2 * which]) * 64.0);
        float scale64 = (float)((double)NBF / (g_scal[3 + 2 * which] * 64.0));

        float acc[4][4][4];
        mma_loop<4>(sT + phase * TILE_BYTES, sT + 2 * TILE_BYTES, tid, acc);

        float bacc = 0.f;
        #pragma unroll
        for (int mf = 0; mf < 4; mf++) {
            int r0 = wr * 64 + mf * 16 + g;
            float x0 = x2s[r0], x1 = x2s[r0 + 8];
            float wx0 = wxs[r0], wx1 = wxs[r0 + 8];
            float sy0 = 0.f, sy1 = 0.f;
            #pragma unroll
            for (int nf = 0; nf < 4; nf++) {
                int c0 = wc * 32 + nf * 8 + 2 * t;
                float y0 = y2s[c0], y1 = y2s[c0 + 1];
                float wy0 = wys[c0], wy1 = wys[c0 + 1];
                float r00 = x0 + y0 - 2.f * acc[mf][nf][0];
                float r01 = x0 + y1 - 2.f * acc[mf][nf][1];
                float r10 = x1 + y0 - 2.f * acc[mf][nf][2];
                float r11 = x1 + y1 - 2.f * acc[mf][nf][3];
                if (r00 < hi64) {
                    if (r00 >= lo64) atomicAdd(&shh[(int)((r00 - lo64) * scale64)], wx0 * wy0);
                    else sy0 += wy0;
                }
                if (r01 < hi64) {
                    if (r01 >= lo64) atomicAdd(&shh[(int)((r01 - lo64) * scale64)], wx0 * wy1);
                    else sy0 += wy1;
                }
                if (r10 < hi64) {
                    if (r10 >= lo64) atomicAdd(&shh[(int)((r10 - lo64) * scale64)], wx1 * wy0);
                    else sy1 += wy0;
                }
                if (r11 < hi64) {
                    if (r11 >= lo64) atomicAdd(&shh[(int)((r11 - lo64) * scale64)], wx1 * wy1);
                    else sy1 += wy1;
                }
            }
            bacc += wx0 * sy0 + wx1 * sy1;
        }
        red[tid] = bacc; __syncthreads();
        for (int off = 128; off; off >>= 1) {
            if (tid < off) red[tid] += red[tid + off];
            __syncthreads();
        }
        if (tid == 0) atomicAdd(&g_below[which], (double)red[0]);
        float* hist = g_hfine + which * NBF;
        for (int i = tid; i < NBF; i += 256) {
            float v = shh[i];
            if (v != 0.f) atomicAdd(&hist[i], v);
            if (phase == 0) shh[i] = 0.f;
        }
        __syncthreads();
    }
}

// ---------------- scan fine hist -> g (512 threads x 8 bins) ----------------
__global__ void k_scanF() {
    int which = blockIdx.x;
    const float* h = g_hfine + which * NBF;
    __shared__ double part[512];
    int tid = threadIdx.x;
    double loc[8], s = 0.0;
    #pragma unroll
    for (int i = 0; i < 8; i++) { loc[i] = h[tid * 8 + i]; s += loc[i]; }
    part[tid] = s; __syncthreads();
    for (int off = 1; off < 512; off <<= 1) {
        double v = (tid >= off) ? part[tid - off] : 0.0;
        __syncthreads();
        part[tid] += v;
        __syncthreads();
    }
    double Wtot = (which == 0) ? g_scal[0] * g_scal[1] : g_scal[1] * g_scal[1];
    double T = 0.5 * Wtot - g_below[which];
    double lo = g_scal[2 + 2 * which], wdt = g_scal[3 + 2 * which];
    double c = tid ? part[tid - 1] : 0.0;
    int b = -1;
    #pragma unroll
    for (int i = 0; i < 8; i++) {
        double nc = c + loc[i];
        if (b < 0 && c < T && nc >= T) b = tid * 8 + i;
        c = nc;
    }
    if (tid == 0 && T <= 0.0) b = 0;
    if (tid == 511 && T > 0.0 && part[511] < T && b < 0) b = NBF - 1;
    if (b >= 0) {
        double tt = lo + (b + 0.5) * (wdt / NBF);
        g_scal[6 + which] = 1.0 / (tt + 1e-8);
    }
}

// ---------------- fused final: shared A row tile, phases ae (B=hB) / aa (B=hA) ------------
#define FOF_X2    0
#define FOF_Y2AE  512
#define FOF_Y2AA  1024
#define FOF_WAE   1536
#define FOF_WAA   2048
#define FOF_RS    2560
#define FOF_TILES 3072
#define SMEM_FIN  (FOF_TILES + 3 * TILE_BYTES)   /* 52224 */

__global__ void __launch_bounds__(256) k_final_fused(
    const float* __restrict__ w, const float* __restrict__ ew)
{
    extern __shared__ __align__(128) char smem[];
    int tid = threadIdx.x;
    int row0 = blockIdx.y * TB, col0 = blockIdx.x * TB;

    stage_one(smem + FOF_TILES,                  g_hA, row0, 1, tid, 128);
    stage_one(smem + FOF_TILES + TILE_BYTES,     g_hB, col0, 1, tid, 128);
    stage_one(smem + FOF_TILES + 2 * TILE_BYTES, g_hA, col0, 1, tid, 128);
    if (tid < TB) {
        ((float*)(smem + FOF_X2))[tid]   = g_x2[row0 + tid];
        ((float*)(smem + FOF_Y2AE))[tid] = g_y2[col0 + tid];
        ((float*)(smem + FOF_Y2AA))[tid] = g_x2[col0 + tid];
        ((float*)(smem + FOF_WAE))[tid]  = ew[col0 + tid];
        ((float*)(smem + FOF_WAA))[tid]  = w[col0 + tid];
        ((float*)(smem + FOF_RS))[tid]   = 0.f;
    }
    __syncthreads();

    uint32_t sT = (uint32_t)__cvta_generic_to_shared(smem) + FOF_TILES;
    const int lane = tid & 31, warp = tid >> 5;
    const int wr = warp >> 2, wc = warp & 3;
    const int g = lane >> 2, t = lane & 3;
    const float* x2s = (const float*)(smem + FOF_X2);
    float* rowsum = (float*)(smem + FOF_RS);

    // fold 1/64 into gammas: exp(-G*d) = exp(-(G/64)*raw)
    float G1 = (float)(g_scal[6] * (1.0 / DF));
    float G2 = (float)(g_scal[7] * (1.0 / DF));

    #pragma unroll
    for (int phase = 0; phase < 2; phase++) {
        const float* y2s = (const float*)(smem + (phase ? FOF_Y2AA : FOF_Y2AE));
        const float* ws  = (const float*)(smem + (phase ? FOF_WAA : FOF_WAE));

        float acc[4][4][4];
        mma_loop<4>(sT, sT + (1 + phase) * TILE_BYTES, tid, acc);

        #pragma unroll
        for (int mf = 0; mf < 4; mf++) {
            int r0 = wr * 64 + mf * 16 + g;
            float x0 = x2s[r0], x1 = x2s[r0 + 8];
            float p0 = 0.f, p1 = 0.f;
            #pragma unroll
            for (int nf = 0; nf < 4; nf++) {
                int c0 = wc * 32 + nf * 8 + 2 * t;
                float y0 = y2s[c0], y1 = y2s[c0 + 1];
                float w0 = ws[c0],  w1 = ws[c0 + 1];
                float r00 = fmaxf(x0 + y0 - 2.f * acc[mf][nf][0], 0.f);
                float r01 = fmaxf(x0 + y1 - 2.f * acc[mf][nf][1], 0.f);
                float r10 = fmaxf(x1 + y0 - 2.f * acc[mf][nf][2], 0.f);
                float r11 = fmaxf(x1 + y1 - 2.f * acc[mf][nf][3], 0.f);
                p0 += (__expf(-G1 * r00) + __expf(-G2 * r00)) * w0
                    + (__expf(-G1 * r01) + __expf(-G2 * r01)) * w1;
                p1 += (__expf(-G1 * r10) + __expf(-G2 * r10)) * w0
                    + (__expf(-G1 * r11) + __expf(-G2 * r11)) * w1;
            }
            atomicAdd(&rowsum[r0], p0);
            atomicAdd(&rowsum[r0 + 8], p1);
        }
        __syncthreads();
        if (tid < TB) {
            float* Sout = phase ? g_Saa : g_Sae;
            atomicAdd(&Sout[row0 + tid], rowsum[tid]);
            rowsum[tid] = 0.f;
        }
        __syncthreads();
    }
}

// ---------------- final combine ----------------
__global__ void k_combine(const float* __restrict__ w, float* __restrict__ out) {
    int i = blockIdx.x * blockDim.x + threadIdx.x;
    if (i < NPTS) {
        float Ws  = (float)g_scal[0];
        float EWs = (float)g_scal[1];
        out[i] = (w[i] / Ws) * (g_Sae[i] / EWs - g_Saa[i] / Ws);
    }
}

// ---------------- host launcher ----------------
extern "C" void kernel_launch(void* const* d_in, const int* in_sizes, int n_in,
                              void* d_out, int out_size)
{
    const float* state   = (const float*)d_in[0];
    const float* action  = (const float*)d_in[1];
    const float* estate  = (const float*)d_in[2];
    const float* eaction = (const float*)d_in[3];
    const float* w       = (const float*)d_in[4];
    const float* ew      = (const float*)d_in[5];
    float* out = (float*)d_out;

    cudaFuncSetAttribute(k_hist_sampled, cudaFuncAttributeMaxDynamicSharedMemorySize, SMEM_HS);
    cudaFuncSetAttribute(k_refine_fused, cudaFuncAttributeMaxDynamicSharedMemorySize, SMEM_RF);
    cudaFuncSetAttribute(k_final_fused,  cudaFuncAttributeMaxDynamicSharedMemorySize, SMEM_FIN);

    dim3 ghs(NTILE, 4, 2);
    dim3 gtile(NTILE, NTILE);

    k_cvt<<<2048, 256>>>(state, action, estate, eaction);
    k_hist_sampled<<<ghs, 256, SMEM_HS>>>(w, ew);
    k_scan0<<<2, 256>>>(w, ew);
    k_refine_fused<<<gtile, 256, SMEM_RF>>>(w, ew);
    k_scanF<<<2, 512>>>();
    k_final_fused<<<gtile, 256, SMEM_FIN>>>(w, ew);
    k_combine<<<16, 256>>>(w, out);
}

// round 17
// speedup vs baseline: 1.3487x; 1.2007x over previous
#include <cuda_runtime.h>
#include <cuda_fp16.h>
#include <math.h>
#include <stdint.h>

#define NPTS 4096
#define DS 48
#define DA 16
#define DF 64
#define TB 128
#define NTILE (NPTS / TB)      /* 32 */
#define NB1 2048               /* coarse bins over [0,16] */
#define SC1 128.0f             /* NB1/16 */
#define NBF 4096               /* fine bins in refine pass */
#define WIN 2                  /* coarse window half-width (bins) */

// ---------------- device scratch ----------------
__device__ __half g_hA[(size_t)NPTS * DF];
__device__ __half g_hB[(size_t)NPTS * DF];
__device__ float  g_x2[NPTS];
__device__ float  g_y2[NPTS];
__device__ float  g_hcoarse[2 * NB1];
__device__ float  g_hfine[2 * NBF];
__device__ double g_below[2];
__device__ double g_scal[8];   // 0 Wsum,1 EWsum,2/3 lo/width ae,4/5 lo/width ee,6 g1,7 g2
__device__ float  g_Sae[NPTS];
__device__ float  g_Saa[NPTS];

// ---------------- mma / ldmatrix helpers (fp16 in, fp32 accum) ----------------
#define MMA_AB(d, A, b0, b1)                                                \
    asm volatile(                                                           \
        "mma.sync.aligned.m16n8k16.row.col.f32.f16.f16.f32 "                \
        "{%0,%1,%2,%3}, {%4,%5,%6,%7}, {%8,%9}, {%0,%1,%2,%3};"             \
        : "+f"((d)[0]), "+f"((d)[1]), "+f"((d)[2]), "+f"((d)[3])            \
        : "r"((A)[0]), "r"((A)[1]), "r"((A)[2]), "r"((A)[3]), "r"(b0), "r"(b1))

__device__ __forceinline__ void ldsm4(uint32_t a, uint32_t d[4]) {
    asm volatile("ldmatrix.sync.aligned.m8n8.x4.shared.b16 {%0,%1,%2,%3}, [%4];"
                 : "=r"(d[0]), "=r"(d[1]), "=r"(d[2]), "=r"(d[3]) : "r"(a));
}

#define SWO(r, kc) ((uint32_t)(r) * 128u + (((uint32_t)(kc)) ^ (((uint32_t)(r) & 7u) << 4)))
#define TILE_BYTES 16384

// ---------------- staging ----------------
__device__ __forceinline__ void stage_one(char* dst, const __half* src,
                                          int row0, int rstride, int tid, int nrows) {
    const uint4* p = (const uint4*)src;
    for (int idx = tid; idx < nrows * 8; idx += 256) {
        int r = idx >> 3, c = idx & 7;
        uint32_t off = (uint32_t)r * 128u + (((uint32_t)c * 16u) ^ (((uint32_t)r & 7u) << 4));
        *(uint4*)(dst + off) = p[(size_t)(row0 + r * rstride) * 8 + c];
    }
}

// ---------------- mainloop: MF m-frags starting at rowbase; single-product fp16 mma ---------
template <int MF>
__device__ __forceinline__ void mma_loop(uint32_t sA, uint32_t sB, int rowbase,
                                         int tid, float acc[MF][4][4]) {
    const int lane = tid & 31, warp = tid >> 5;
    const int wc = warp & 3;

    #pragma unroll
    for (int mf = 0; mf < MF; mf++)
        #pragma unroll
        for (int nf = 0; nf < 4; nf++)
            #pragma unroll
            for (int u = 0; u < 4; u++) acc[mf][nf][u] = 0.f;

    const int aRow = lane & 15;
    const int aKc  = (lane >> 4) << 4;
    const int bRow = ((lane & 16) >> 1) + (lane & 7);
    const int bKc  = (lane & 8) ? 16 : 0;

    #pragma unroll
    for (int ks = 0; ks < 4; ks++) {
        const int kc0 = ks * 32;
        uint32_t BH[2][4];
        #pragma unroll
        for (int p = 0; p < 2; p++) {
            uint32_t off = SWO(wc * 32 + p * 16 + bRow, kc0 + bKc);
            ldsm4(sB + off, BH[p]);
        }
        #pragma unroll
        for (int mf = 0; mf < MF; mf++) {
            uint32_t off = SWO(rowbase + mf * 16 + aRow, kc0 + aKc);
            uint32_t AH[4];
            ldsm4(sA + off, AH);
            #pragma unroll
            for (int p = 0; p < 2; p++) {
                MMA_AB(acc[mf][2 * p],     AH, BH[p][0], BH[p][1]);
                MMA_AB(acc[mf][2 * p + 1], AH, BH[p][2], BH[p][3]);
            }
        }
    }
}

// ---------------- convert inputs to fp16 + row norms + zero accumulators ----------------
__global__ void k_cvt(const float* __restrict__ ss, const float* __restrict__ aa_,
                      const float* __restrict__ es, const float* __restrict__ ea) {
    __shared__ float cvt_part[8];
    int tid = threadIdx.x;
    int gid = blockIdx.x * 256 + tid;
    if (gid < 2 * NB1) g_hcoarse[gid] = 0.f;
    if (gid < 2 * NBF) g_hfine[gid]   = 0.f;
    if (gid < NPTS)  { g_Saa[gid] = 0.f; g_Sae[gid] = 0.f; }
    if (gid < 2)       g_below[gid]   = 0.0;

    int gr = blockIdx.x * 4 + (tid >> 6);
    int k  = tid & 63;
    bool isA = (gr < NPTS);
    int r = isA ? gr : gr - NPTS;
    const float* sp = isA ? ss : es;
    const float* ap = isA ? aa_ : ea;
    __half* hp = isA ? g_hA : g_hB;

    float v = (k < DS) ? sp[(size_t)r * DS + k] : ap[(size_t)r * DA + (k - DS)];
    hp[(size_t)r * DF + k] = __float2half(v);

    float sq = v * v;
    #pragma unroll
    for (int off = 16; off; off >>= 1) sq += __shfl_xor_sync(0xFFFFFFFF, sq, off);
    if ((tid & 31) == 0) cvt_part[tid >> 5] = sq;
    __syncthreads();
    if ((tid & 63) == 0) {
        float s = cvt_part[(tid >> 5)] + cvt_part[(tid >> 5) + 1];
        if (isA) g_x2[r] = s; else g_y2[r] = s;
    }
}

// ---------------- sampled coarse hist via fp16 MMA, M=64 tiles ----------------
#define HOF_X2    0
#define HOF_WX    256
#define HOF_Y2    512
#define HOF_WY    1024
#define HOF_HIST  1536
#define HOF_TILES 17920
#define SMEM_HS   (HOF_TILES + 8192 + 16384)   /* 42496 */

__global__ void __launch_bounds__(256) k_hist_sampled(
    const float* __restrict__ w, const float* __restrict__ ew)
{
    extern __shared__ __align__(128) char smem[];
    int tid = threadIdx.x;
    bool ae = (blockIdx.z == 0);
    int col0 = blockIdx.x * TB;
    int sbase = blockIdx.y * 64;

    const __half* Ah = ae ? g_hA : g_hB;
    const float* x2p = ae ? g_x2 : g_y2;
    const float* wxp = ae ? w : ew;

    float* shh = (float*)(smem + HOF_HIST);
    for (int i = tid; i < 2 * NB1; i += 256) shh[i] = 0.f;

    stage_one(smem + HOF_TILES,        Ah,   sbase * 16, 16, tid, 64);
    stage_one(smem + HOF_TILES + 8192, g_hB, col0,       1,  tid, 128);
    if (tid < 64) {
        ((float*)(smem + HOF_X2))[tid] = x2p[(sbase + tid) * 16];
        ((float*)(smem + HOF_WX))[tid] = wxp[(sbase + tid) * 16];
    }
    if (tid < TB) {
        ((float*)(smem + HOF_Y2))[tid] = g_y2[col0 + tid];
        ((float*)(smem + HOF_WY))[tid] = ew[col0 + tid];
    }
    __syncthreads();

    uint32_t sT = (uint32_t)__cvta_generic_to_shared(smem) + HOF_TILES;
    const int lane = tid & 31, warp = tid >> 5;
    const int wr = warp >> 2, wc = warp & 3;
    const int g = lane >> 2, t = lane & 3;

    float acc[2][4][4];
    mma_loop<2>(sT, sT + 8192, wr * 32, tid, acc);

    const float* x2s = (const float*)(smem + HOF_X2);
    const float* wxs = (const float*)(smem + HOF_WX);
    const float* y2s = (const float*)(smem + HOF_Y2);
    const float* wys = (const float*)(smem + HOF_WY);
    float* myh = shh + (warp & 1) * NB1;

    #pragma unroll
    for (int mf = 0; mf < 2; mf++) {
        int r0 = wr * 32 + mf * 16 + g;
        float x0 = x2s[r0], x1 = x2s[r0 + 8];
        float wx0 = wxs[r0], wx1 = wxs[r0 + 8];
        #pragma unroll
        for (int nf = 0; nf < 4; nf++) {
            int c0 = wc * 32 + nf * 8 + 2 * t;
            float y0 = y2s[c0], y1 = y2s[c0 + 1];
            float wy0 = wys[c0], wy1 = wys[c0 + 1];
            float d00 = fmaxf(x0 + y0 - 2.f * acc[mf][nf][0], 0.f) * (1.f / DF);
            float d01 = fmaxf(x0 + y1 - 2.f * acc[mf][nf][1], 0.f) * (1.f / DF);
            float d10 = fmaxf(x1 + y0 - 2.f * acc[mf][nf][2], 0.f) * (1.f / DF);
            float d11 = fmaxf(x1 + y1 - 2.f * acc[mf][nf][3], 0.f) * (1.f / DF);
            atomicAdd(&myh[min((int)(d00 * SC1), NB1 - 1)], wx0 * wy0);
            atomicAdd(&myh[min((int)(d01 * SC1), NB1 - 1)], wx0 * wy1);
            atomicAdd(&myh[min((int)(d10 * SC1), NB1 - 1)], wx1 * wy0);
            atomicAdd(&myh[min((int)(d11 * SC1), NB1 - 1)], wx1 * wy1);
        }
    }
    __syncthreads();
    float* hist = g_hcoarse + (ae ? 0 : NB1);
    for (int i = tid; i < NB1; i += 256) {
        float v = shh[i] + shh[i + NB1];
        if (v != 0.f) atomicAdd(&hist[i], v);
    }
}

// ---------------- scan coarse hist -> window (±WIN bins); also weight sums ----------------
__global__ void k_scan0(const float* __restrict__ w, const float* __restrict__ ew) {
    int which = blockIdx.x;
    int tid = threadIdx.x;
    __shared__ double part[256];

    {
        const float* src = which ? ew : w;
        double s = 0.0;
        for (int i = tid; i < NPTS; i += 256) s += src[i];
        part[tid] = s; __syncthreads();
        for (int off = 128; off; off >>= 1) {
            if (tid < off) part[tid] += part[tid + off];
            __syncthreads();
        }
        if (tid == 0) g_scal[which] = part[0];
        __syncthreads();
    }

    const float* h = g_hcoarse + which * NB1;
    double loc[8], s = 0.0;
    #pragma unroll
    for (int i = 0; i < 8; i++) { loc[i] = h[tid * 8 + i]; s += loc[i]; }
    part[tid] = s; __syncthreads();
    for (int off = 1; off < 256; off <<= 1) {
        double v = (tid >= off) ? part[tid - off] : 0.0;
        __syncthreads();
        part[tid] += v;
        __syncthreads();
    }
    double T = 0.5 * part[255];
    double c = tid ? part[tid - 1] : 0.0;
    int b = -1;
    #pragma unroll
    for (int i = 0; i < 8; i++) {
        double nc = c + loc[i];
        if (b < 0 && c < T && nc >= T) b = tid * 8 + i;
        c = nc;
    }
    if (b >= 0) {
        int blo = b > WIN ? b - WIN : 0;
        int bhi = b + WIN + 1 > NB1 ? NB1 : b + WIN + 1;
        g_scal[2 + 2 * which] = blo * (16.0 / NB1);
        g_scal[3 + 2 * which] = (bhi - blo) * (16.0 / NB1);
    }
}

// ---------------- fused refine: 3 CTAs/SM, mf-chunked, branch-minimal epilogue -------------
#define ROF_X2AE  0
#define ROF_X2EE  512
#define ROF_Y2    1024
#define ROF_WXAE  1536
#define ROF_WXEE  2048
#define ROF_WY    2560
#define ROF_HIST  3072                       /* NBF*4 = 16384 */
#define ROF_TILES 19456
#define SMEM_RF   (ROF_TILES + 3 * TILE_BYTES)   /* 68608 */

__global__ void __launch_bounds__(256, 3) k_refine_fused(
    const float* __restrict__ w, const float* __restrict__ ew)
{
    extern __shared__ __align__(128) char smem[];
    __shared__ float red[256];
    int tid = threadIdx.x;
    int row0 = blockIdx.y * TB, col0 = blockIdx.x * TB;

    float* shh = (float*)(smem + ROF_HIST);
    for (int i = tid; i < NBF; i += 256) shh[i] = 0.f;

    stage_one(smem + ROF_TILES,                  g_hA, row0, 1, tid, 128);  // A_ae
    stage_one(smem + ROF_TILES + TILE_BYTES,     g_hB, row0, 1, tid, 128);  // A_ee
    stage_one(smem + ROF_TILES + 2 * TILE_BYTES, g_hB, col0, 1, tid, 128);  // B (shared)
    if (tid < TB) {
        ((float*)(smem + ROF_X2AE))[tid] = g_x2[row0 + tid];
        ((float*)(smem + ROF_X2EE))[tid] = g_y2[row0 + tid];
        ((float*)(smem + ROF_Y2))[tid]   = g_y2[col0 + tid];
        ((float*)(smem + ROF_WXAE))[tid] = w[row0 + tid];
        ((float*)(smem + ROF_WXEE))[tid] = ew[row0 + tid];
        ((float*)(smem + ROF_WY))[tid]   = ew[col0 + tid];
    }
    __syncthreads();

    uint32_t sT = (uint32_t)__cvta_generic_to_shared(smem) + ROF_TILES;
    const int lane = tid & 31, warp = tid >> 5;
    const int wr = warp >> 2, wc = warp & 3;
    const int g = lane >> 2, t = lane & 3;
    const float* y2s = (const float*)(smem + ROF_Y2);
    const float* wys = (const float*)(smem + ROF_WY);

    #pragma unroll
    for (int phase = 0; phase < 2; phase++) {
        int which = phase;
        const float* x2s = (const float*)(smem + (phase ? ROF_X2EE : ROF_X2AE));
        const float* wxs = (const float*)(smem + (phase ? ROF_WXEE : ROF_WXAE));
        float lo64    = (float)(g_scal[2 + 2 * which] * 64.0);
        float hi64    = (float)((g_scal[2 + 2 * which] + g_scal[3 + 2 * which]) * 64.0);
        float scale64 = (float)((double)NBF / (g_scal[3 + 2 * which] * 64.0));

        float bacc = 0.f;
        #pragma unroll
        for (int chunk = 0; chunk < 2; chunk++) {
            int rowbase = wr * 64 + chunk * 32;
            float acc[2][4][4];
            mma_loop<2>(sT + phase * TILE_BYTES, sT + 2 * TILE_BYTES, rowbase, tid, acc);

            #pragma unroll
            for (int mf = 0; mf < 2; mf++) {
                int r0 = rowbase + mf * 16 + g;
                float x0 = x2s[r0], x1 = x2s[r0 + 8];
                float wx0 = wxs[r0], wx1 = wxs[r0 + 8];
                float sy0 = 0.f, sy1 = 0.f;
                #pragma unroll
                for (int nf = 0; nf < 4; nf++) {
                    int c0 = wc * 32 + nf * 8 + 2 * t;
                    float y0 = y2s[c0], y1 = y2s[c0 + 1];
                    float wy0 = wys[c0], wy1 = wys[c0 + 1];
                    float r00 = x0 + y0 - 2.f * acc[mf][nf][0];
                    float r01 = x0 + y1 - 2.f * acc[mf][nf][1];
                    float r10 = x1 + y0 - 2.f * acc[mf][nf][2];
                    float r11 = x1 + y1 - 2.f * acc[mf][nf][3];
                    // branchless below-mass
                    sy0 += (r00 < lo64) ? wy0 : 0.f;
                    sy0 += (r01 < lo64) ? wy1 : 0.f;
                    sy1 += (r10 < lo64) ? wy0 : 0.f;
                    sy1 += (r11 < lo64) ? wy1 : 0.f;
                    // rare in-window atomic, single predicate each
                    if (r00 >= lo64 && r00 < hi64)
                        atomicAdd(&shh[min((int)((r00 - lo64) * scale64), NBF - 1)], wx0 * wy0);
                    if (r01 >= lo64 && r01 < hi64)
                        atomicAdd(&shh[min((int)((r01 - lo64) * scale64), NBF - 1)], wx0 * wy1);
                    if (r10 >= lo64 && r10 < hi64)
                        atomicAdd(&shh[min((int)((r10 - lo64) * scale64), NBF - 1)], wx1 * wy0);
                    if (r11 >= lo64 && r11 < hi64)
                        atomicAdd(&shh[min((int)((r11 - lo64) * scale64), NBF - 1)], wx1 * wy1);
                }
                bacc += wx0 * sy0 + wx1 * sy1;
            }
        }
        red[tid] = bacc; __syncthreads();
        for (int off = 128; off; off >>= 1) {
            if (tid < off) red[tid] += red[tid + off];
            __syncthreads();
        }
        if (tid == 0) atomicAdd(&g_below[which], (double)red[0]);
        float* hist = g_hfine + which * NBF;
        for (int i = tid; i < NBF; i += 256) {
            float v = shh[i];
            if (v != 0.f) atomicAdd(&hist[i], v);
            if (phase == 0) shh[i] = 0.f;
        }
        __syncthreads();
    }
}

// ---------------- scan fine hist -> g (512 threads x 8 bins) ----------------
__global__ void k_scanF() {
    int which = blockIdx.x;
    const float* h = g_hfine + which * NBF;
    __shared__ double part[512];
    int tid = threadIdx.x;
    double loc[8], s = 0.0;
    #pragma unroll
    for (int i = 0; i < 8; i++) { loc[i] = h[tid * 8 + i]; s += loc[i]; }
    part[tid] = s; __syncthreads();
    for (int off = 1; off < 512; off <<= 1) {
        double v = (tid >= off) ? part[tid - off] : 0.0;
        __syncthreads();
        part[tid] += v;
        __syncthreads();
    }
    double Wtot = (which == 0) ? g_scal[0] * g_scal[1] : g_scal[1] * g_scal[1];
    double T = 0.5 * Wtot - g_below[which];
    double lo = g_scal[2 + 2 * which], wdt = g_scal[3 + 2 * which];
    double c = tid ? part[tid - 1] : 0.0;
    int b = -1;
    #pragma unroll
    for (int i = 0; i < 8; i++) {
        double nc = c + loc[i];
        if (b < 0 && c < T && nc >= T) b = tid * 8 + i;
        c = nc;
    }
    if (tid == 0 && T <= 0.0) b = 0;
    if (tid == 511 && T > 0.0 && part[511] < T && b < 0) b = NBF - 1;
    if (b >= 0) {
        double tt = lo + (b + 0.5) * (wdt / NBF);
        g_scal[6 + which] = 1.0 / (tt + 1e-8);
    }
}

// ---------------- fused final: shared A row tile, phases ae (B=hB) / aa (B=hA) ------------
#define FOF_X2    0
#define FOF_Y2AE  512
#define FOF_Y2AA  1024
#define FOF_WAE   1536
#define FOF_WAA   2048
#define FOF_RS    2560
#define FOF_TILES 3072
#define SMEM_FIN  (FOF_TILES + 3 * TILE_BYTES)   /* 52224 */

__global__ void __launch_bounds__(256) k_final_fused(
    const float* __restrict__ w, const float* __restrict__ ew)
{
    extern __shared__ __align__(128) char smem[];
    int tid = threadIdx.x;
    int row0 = blockIdx.y * TB, col0 = blockIdx.x * TB;

    stage_one(smem + FOF_TILES,                  g_hA, row0, 1, tid, 128);
    stage_one(smem + FOF_TILES + TILE_BYTES,     g_hB, col0, 1, tid, 128);
    stage_one(smem + FOF_TILES + 2 * TILE_BYTES, g_hA, col0, 1, tid, 128);
    if (tid < TB) {
        ((float*)(smem + FOF_X2))[tid]   = g_x2[row0 + tid];
        ((float*)(smem + FOF_Y2AE))[tid] = g_y2[col0 + tid];
        ((float*)(smem + FOF_Y2AA))[tid] = g_x2[col0 + tid];
        ((float*)(smem + FOF_WAE))[tid]  = ew[col0 + tid];
        ((float*)(smem + FOF_WAA))[tid]  = w[col0 + tid];
        ((float*)(smem + FOF_RS))[tid]   = 0.f;
    }
    __syncthreads();

    uint32_t sT = (uint32_t)__cvta_generic_to_shared(smem) + FOF_TILES;
    const int lane = tid & 31, warp = tid >> 5;
    const int wr = warp >> 2, wc = warp & 3;
    const int g = lane >> 2, t = lane & 3;
    const float* x2s = (const float*)(smem + FOF_X2);
    float* rowsum = (float*)(smem + FOF_RS);

    float G1 = (float)(g_scal[6] * (1.0 / DF));
    float G2 = (float)(g_scal[7] * (1.0 / DF));

    #pragma unroll
    for (int phase = 0; phase < 2; phase++) {
        const float* y2s = (const float*)(smem + (phase ? FOF_Y2AA : FOF_Y2AE));
        const float* ws  = (const float*)(smem + (phase ? FOF_WAA : FOF_WAE));

        float acc[4][4][4];
        mma_loop<4>(sT, sT + (1 + phase) * TILE_BYTES, wr * 64, tid, acc);

        #pragma unroll
        for (int mf = 0; mf < 4; mf++) {
            int r0 = wr * 64 + mf * 16 + g;
            float x0 = x2s[r0], x1 = x2s[r0 + 8];
            float p0 = 0.f, p1 = 0.f;
            #pragma unroll
            for (int nf = 0; nf < 4; nf++) {
                int c0 = wc * 32 + nf * 8 + 2 * t;
                float y0 = y2s[c0], y1 = y2s[c0 + 1];
                float w0 = ws[c0],  w1 = ws[c0 + 1];
                float r00 = fmaxf(x0 + y0 - 2.f * acc[mf][nf][0], 0.f);
                float r01 = fmaxf(x0 + y1 - 2.f * acc[mf][nf][1], 0.f);
                float r10 = fmaxf(x1 + y0 - 2.f * acc[mf][nf][2], 0.f);
                float r11 = fmaxf(x1 + y1 - 2.f * acc[mf][nf][3], 0.f);
                p0 += (__expf(-G1 * r00) + __expf(-G2 * r00)) * w0
                    + (__expf(-G1 * r01) + __expf(-G2 * r01)) * w1;
                p1 += (__expf(-G1 * r10) + __expf(-G2 * r10)) * w0
                    + (__expf(-G1 * r11) + __expf(-G2 * r11)) * w1;
            }
            atomicAdd(&rowsum[r0], p0);
            atomicAdd(&rowsum[r0 + 8], p1);
        }
        __syncthreads();
        if (tid < TB) {
            float* Sout = phase ? g_Saa : g_Sae;
            atomicAdd(&Sout[row0 + tid], rowsum[tid]);
            rowsum[tid] = 0.f;
        }
        __syncthreads();
    }
}

// ---------------- final combine ----------------
__global__ void k_combine(const float* __restrict__ w, float* __restrict__ out) {
    int i = blockIdx.x * blockDim.x + threadIdx.x;
    if (i < NPTS) {
        float Ws  = (float)g_scal[0];
        float EWs = (float)g_scal[1];
        out[i] = (w[i] / Ws) * (g_Sae[i] / EWs - g_Saa[i] / Ws);
    }
}

// ---------------- host launcher ----------------
extern "C" void kernel_launch(void* const* d_in, const int* in_sizes, int n_in,
                              void* d_out, int out_size)
{
    const float* state   = (const float*)d_in[0];
    const float* action  = (const float*)d_in[1];
    const float* estate  = (const float*)d_in[2];
    const float* eaction = (const float*)d_in[3];
    const float* w       = (const float*)d_in[4];
    const float* ew      = (const float*)d_in[5];
    float* out = (float*)d_out;

    cudaFuncSetAttribute(k_hist_sampled, cudaFuncAttributeMaxDynamicSharedMemorySize, SMEM_HS);
    cudaFuncSetAttribute(k_refine_fused, cudaFuncAttributeMaxDynamicSharedMemorySize, SMEM_RF);
    cudaFuncSetAttribute(k_final_fused,  cudaFuncAttributeMaxDynamicSharedMemorySize, SMEM_FIN);

    dim3 ghs(NTILE, 4, 2);
    dim3 gtile(NTILE, NTILE);

    k_cvt<<<2048, 256>>>(state, action, estate, eaction);
    k_hist_sampled<<<ghs, 256, SMEM_HS>>>(w, ew);
    k_scan0<<<2, 256>>>(w, ew);
    k_refine_fused<<<gtile, 256, SMEM_RF>>>(w, ew);
    k_scanF<<<2, 512>>>();
    k_final_fused<<<gtile, 256, SMEM_FIN>>>(w, ew);
    k_combine<<<16, 256>>>(w, out);
}